// round 2
// baseline (speedup 1.0000x reference)
#include <cuda_runtime.h>
#include <stdint.h>

// image: [16, 3, 1024, 1024] fp32
// camera_index: [16] int32 (JAX x64-disabled demotes int64 -> int32)
// weight: [34, 3] fp32
// bias:   [34, 3] fp32
// out = image * weight[cam[b], c] + bias[cam[b], c]

static constexpr int B  = 16;
static constexpr int C  = 3;
static constexpr int HW = 1024 * 1024;       // elements per plane
static constexpr int HW4 = HW / 4;           // float4 per plane = 262144

static constexpr int TPB = 256;
static constexpr int V_PER_THREAD = 4;       // float4 per thread per block
// blocks in x per plane: 262144 / (256*4) = 256
static constexpr int BLK_X = HW4 / (TPB * V_PER_THREAD);

__global__ __launch_bounds__(TPB) void colorcal_kernel(
    const float4* __restrict__ img,
    const int* __restrict__ cam_idx,
    const float* __restrict__ weight,
    const float* __restrict__ bias,
    float4* __restrict__ out)
{
    const int plane = blockIdx.y;            // 0..47
    const int b = plane / C;
    const int c = plane - b * C;

    const int cam = cam_idx[b];              // uniform per block
    const float s = __ldg(&weight[cam * C + c]);
    const float t = __ldg(&bias[cam * C + c]);

    const float4* __restrict__ src = img + (size_t)plane * HW4;
    float4* __restrict__ dst       = out + (size_t)plane * HW4;

    const int base = blockIdx.x * TPB + threadIdx.x;
    const int stride = BLK_X * TPB;

    #pragma unroll
    for (int v = 0; v < V_PER_THREAD; v++) {
        const int i = base + v * stride;
        float4 x = __ldg(&src[i]);
        float4 y;
        y.x = fmaf(x.x, s, t);
        y.y = fmaf(x.y, s, t);
        y.z = fmaf(x.z, s, t);
        y.w = fmaf(x.w, s, t);
        dst[i] = y;
    }
}

extern "C" void kernel_launch(void* const* d_in, const int* in_sizes, int n_in,
                              void* d_out, int out_size)
{
    const float4* img = (const float4*)d_in[0];
    const int*    cam = (const int*)d_in[1];
    const float*  w   = (const float*)d_in[2];
    const float*  bia = (const float*)d_in[3];
    float4*       out = (float4*)d_out;

    dim3 grid(BLK_X, B * C, 1);
    colorcal_kernel<<<grid, TPB>>>(img, cam, w, bia, out);
}

// round 3
// speedup vs baseline: 1.0258x; 1.0258x over previous
#include <cuda_runtime.h>
#include <stdint.h>

// image: [16, 3, 1024, 1024] fp32
// camera_index: [16] int32
// weight/bias: [34, 3] fp32
// out = image * weight[cam[b], c] + bias[cam[b], c]

static constexpr int B  = 16;
static constexpr int C  = 3;
static constexpr int HW = 1024 * 1024;
static constexpr int HW4 = HW / 4;           // 262144 float4 per plane

static constexpr int TPB = 256;
static constexpr int V_PER_THREAD = 8;       // 8 x float4 per thread
static constexpr int BLK_X = HW4 / (TPB * V_PER_THREAD);   // 128 blocks per plane

__global__ __launch_bounds__(TPB) void colorcal_kernel(
    const float4* __restrict__ img,
    const int* __restrict__ cam_idx,
    const float* __restrict__ weight,
    const float* __restrict__ bias,
    float4* __restrict__ out)
{
    const int plane = blockIdx.y;            // 0..47
    const int b = plane / C;
    const int c = plane - b * C;

    const int cam = cam_idx[b];              // uniform per block
    const float s = __ldg(&weight[cam * C + c]);
    const float t = __ldg(&bias[cam * C + c]);

    const float4* __restrict__ src = img + (size_t)plane * HW4;
    float4* __restrict__ dst       = out + (size_t)plane * HW4;

    const int base = blockIdx.x * TPB + threadIdx.x;
    const int stride = BLK_X * TPB;          // 32768 float4

    // Front-batch all 8 loads (max MLP), then stores.
    float4 x[V_PER_THREAD];
    #pragma unroll
    for (int v = 0; v < V_PER_THREAD; v++)
        x[v] = __ldcs(&src[base + v * stride]);

    #pragma unroll
    for (int v = 0; v < V_PER_THREAD; v++) {
        float4 y;
        y.x = fmaf(x[v].x, s, t);
        y.y = fmaf(x[v].y, s, t);
        y.z = fmaf(x[v].z, s, t);
        y.w = fmaf(x[v].w, s, t);
        __stcs(&dst[base + v * stride], y);
    }
}

extern "C" void kernel_launch(void* const* d_in, const int* in_sizes, int n_in,
                              void* d_out, int out_size)
{
    const float4* img = (const float4*)d_in[0];
    const int*    cam = (const int*)d_in[1];
    const float*  w   = (const float*)d_in[2];
    const float*  bia = (const float*)d_in[3];
    float4*       out = (float4*)d_out;

    dim3 grid(BLK_X, B * C, 1);
    colorcal_kernel<<<grid, TPB>>>(img, cam, w, bia, out);
}